// round 1
// baseline (speedup 1.0000x reference)
#include <cuda_runtime.h>

#define N_NODES 131072
#define NPER    4096
#define NBATCH  32
#define D       32
#define NREL    10
#define NG      14   // num_g_rels

// ---------------- scratch (device globals; no allocation allowed) ----------------
__device__ __align__(16) float g_w1[N_NODES * D];
__device__ __align__(16) float g_U [N_NODES * D];
__device__ __align__(16) float g_V [N_NODES * D];
__device__ __align__(16) float g_H [N_NODES * D];
__device__ __align__(16) float g_nf[N_NODES * D];
__device__ float g_M1[D * D];     // (W2a - W2b) @ W_line
__device__ float g_M2[D * D];     // W2c @ W_line
__device__ float g_M3[D * D];     // self_loop_w @ W_line
__device__ float g_Cw[NREL * D];  // (attn_r @ (W2a+W2b) + b2) @ W_line

// ---------------- prep: derived matrices ----------------
__global__ void k_prep(const float* __restrict__ W2, const float* __restrict__ b2,
                       const float* __restrict__ attn, const float* __restrict__ SL,
                       const float* __restrict__ Wl) {
    __shared__ float Cs[NREL * D];
    int t = threadIdx.x;
    if (t < NREL * D) {
        int r = t / D, j = t % D;
        float acc = b2[j];
        #pragma unroll
        for (int k = 0; k < D; k++)
            acc += attn[r * D + k] * (W2[k * D + j] + W2[(D + k) * D + j]);
        Cs[t] = acc;
    }
    __syncthreads();
    if (t < D * D) {
        int k = t / D, d = t % D;
        float m1 = 0.f, m2 = 0.f, m3 = 0.f;
        #pragma unroll
        for (int j = 0; j < D; j++) {
            float wl = Wl[j * D + d];
            m1 += (W2[k * D + j] - W2[(D + k) * D + j]) * wl;
            m2 += W2[(2 * D + k) * D + j] * wl;
            m3 += SL[k * D + j] * wl;
        }
        g_M1[t] = m1; g_M2[t] = m2; g_M3[t] = m3;
    }
    if (t < NREL * D) {
        int r = t / D, d = t % D;
        float acc = 0.f;
        #pragma unroll
        for (int j = 0; j < D; j++) acc += Cs[r * D + j] * Wl[j * D + d];
        g_Cw[t] = acc;
    }
}

// ---------------- zero accumulators ----------------
__global__ void k_zero_acc() {
    int i = blockIdx.x * blockDim.x + threadIdx.x;
    int stride = gridDim.x * blockDim.x;
    const int total = N_NODES * D / 4;
    float4 z = make_float4(0.f, 0.f, 0.f, 0.f);
    for (int j = i; j < total; j += stride) {
        reinterpret_cast<float4*>(g_U)[j] = z;
        reinterpret_cast<float4*>(g_V)[j] = z;
        reinterpret_cast<float4*>(g_H)[j] = z;
    }
}

// ---------------- node precompute: w1 = feat @ W_w + b_w ----------------
__global__ void k_w1(const float* __restrict__ feat, const float* __restrict__ Ww,
                     const float* __restrict__ bw, int n_nodes) {
    __shared__ float Ws[D * D];
    __shared__ float bs[D];
    for (int i = threadIdx.x; i < D * D; i += blockDim.x) Ws[i] = Ww[i];
    if (threadIdx.x < D) bs[threadIdx.x] = bw[threadIdx.x];
    __syncthreads();
    int lane = threadIdx.x & 31;
    int warp = (blockIdx.x * blockDim.x + threadIdx.x) >> 5;
    int nw   = (gridDim.x * blockDim.x) >> 5;
    for (int n = warp; n < n_nodes; n += nw) {
        float f = feat[n * D + lane];
        float acc = bs[lane];
        #pragma unroll
        for (int k = 0; k < D; k++)
            acc += __shfl_sync(0xffffffffu, f, k) * Ws[k * D + lane];
        g_w1[n * D + lane] = acc;
    }
}

// ---------------- edge stage: U/V/H accumulation ----------------
__global__ void k_edge(const int* __restrict__ src, const int* __restrict__ dst,
                       const int* __restrict__ ety, const float* __restrict__ norm,
                       const float* __restrict__ attn, int nE) {
    __shared__ float et_s[NREL * D];
    __shared__ float cw_s[NREL * D];
    for (int i = threadIdx.x; i < NREL * D; i += blockDim.x) {
        et_s[i] = attn[i];
        cw_s[i] = g_Cw[i];
    }
    __syncthreads();
    int lane = threadIdx.x & 31;
    int warp = (blockIdx.x * blockDim.x + threadIdx.x) >> 5;
    int nw   = (gridDim.x * blockDim.x) >> 5;
    for (int e = warp; e < nE; e += nw) {
        int   s  = src[e];
        int   d  = dst[e];
        int   r  = ety[e];
        float nm = norm[e];
        float f  = g_w1[s * D + lane];           // coalesced 128B gather (L2-resident)
        float t1 = nm * f;
        atomicAdd(&g_U[d * D + lane], t1);
        atomicAdd(&g_V[d * D + lane], t1 * et_s[r * D + lane]);
        atomicAdd(&g_H[d * D + lane], nm * cw_s[r * D + lane]);
    }
}

// ---------------- combine: nf = relu(U@M1 + V@M2 + feat@M3 + H + b_line) ----------------
__global__ void k_nf(const float* __restrict__ feat, const float* __restrict__ bline,
                     int n_nodes) {
    __shared__ float M1s[D * D], M2s[D * D], M3s[D * D], bs[D];
    for (int i = threadIdx.x; i < D * D; i += blockDim.x) {
        M1s[i] = g_M1[i]; M2s[i] = g_M2[i]; M3s[i] = g_M3[i];
    }
    if (threadIdx.x < D) bs[threadIdx.x] = bline[threadIdx.x];
    __syncthreads();
    int lane = threadIdx.x & 31;
    int warp = (blockIdx.x * blockDim.x + threadIdx.x) >> 5;
    int nw   = (gridDim.x * blockDim.x) >> 5;
    for (int n = warp; n < n_nodes; n += nw) {
        float u = g_U[n * D + lane];
        float v = g_V[n * D + lane];
        float f = feat[n * D + lane];
        float acc = g_H[n * D + lane] + bs[lane];
        #pragma unroll
        for (int k = 0; k < D; k++) {
            acc += __shfl_sync(0xffffffffu, u, k) * M1s[k * D + lane];
            acc += __shfl_sync(0xffffffffu, v, k) * M2s[k * D + lane];
            acc += __shfl_sync(0xffffffffu, f, k) * M3s[k * D + lane];
        }
        g_nf[n * D + lane] = fmaxf(acc, 0.f);
    }
}

// ---------------- zero out1 + out2 region of d_out ----------------
__global__ void k_zero_out(float* __restrict__ out) {
    int i = blockIdx.x * blockDim.x + threadIdx.x;
    const int total = NBATCH * (NG + 1) * D + NBATCH * D;  // 15360 + 1024
    if (i < total) out[i] = 0.f;
}

// ---------------- scatter batch_rel_emds + target_rel_emd ----------------
__global__ void k_scatter(const int* __restrict__ idx2, const int* __restrict__ f2,
                          const int* __restrict__ tar, float* __restrict__ out,
                          int n_nodes) {
    int i = blockIdx.x * blockDim.x + threadIdx.x;
    if (i >= n_nodes) return;
    int b = i / NPER;
    if (idx2[i] != 0) {
        int slot = f2[i] + 1;                    // index_offset = 1
        if (slot <= NG) {                        // slot NG+1 is the dump row (dropped)
            float* o = out + (b * (NG + 1) + slot) * D;
            const float* s = g_nf + (size_t)i * D;
            #pragma unroll
            for (int d = 0; d < D; d++) o[d] = s[d];
        }
    }
    if (tar[i] == 1) {
        float* o = out + NBATCH * (NG + 1) * D + b * D;
        const float* s = g_nf + (size_t)i * D;
        #pragma unroll
        for (int d = 0; d < D; d++) atomicAdd(&o[d], s[d]);
    }
}

// ---------------- per-batch path softmax aggregation ----------------
__global__ void k_path(const int* __restrict__ idx1, const float* __restrict__ zero_path,
                       float* __restrict__ out) {
    __shared__ float sc[NPER];        // 16KB scores
    __shared__ float tgt[D];
    __shared__ float red[256];
    __shared__ float wacc[8][D];
    int b = blockIdx.x;
    int t = threadIdx.x;
    const int OUT2 = NBATCH * (NG + 1) * D;
    const int OUT3 = OUT2 + NBATCH * D;
    if (t < D) tgt[t] = out[OUT2 + b * D + t];   // target_rel_emd[b], written by k_scatter
    __syncthreads();
    size_t base = (size_t)b * NPER;

    // scores
    for (int i = t; i < NPER; i += 256) {
        float s = -1e30f;
        if (idx1[base + i] == 1) {
            const float* row = g_nf + (base + i) * D;
            float acc = 0.f;
            #pragma unroll
            for (int k = 0; k < D; k++) acc += row[k] * tgt[k];
            s = acc;
        }
        sc[i] = s;
    }
    __syncthreads();

    // block max
    float m = -1e30f;
    for (int i = t; i < NPER; i += 256) m = fmaxf(m, sc[i]);
    red[t] = m; __syncthreads();
    for (int off = 128; off > 0; off >>= 1) {
        if (t < off) red[t] = fmaxf(red[t], red[t + off]);
        __syncthreads();
    }
    float mglob = red[0];
    __syncthreads();

    if (mglob < -1e29f) {                        // no path nodes -> zero_path
        if (t < D) out[OUT3 + b * D + t] = zero_path[t];
        return;
    }

    // exp + sum
    float ssum = 0.f;
    for (int i = t; i < NPER; i += 256) {
        float e = (sc[i] > -1e29f) ? __expf(sc[i] - mglob) : 0.f;
        sc[i] = e;
        ssum += e;
    }
    red[t] = ssum; __syncthreads();
    for (int off = 128; off > 0; off >>= 1) {
        if (t < off) red[t] += red[t + off];
        __syncthreads();
    }
    float sglob = red[0];
    __syncthreads();

    // weighted aggregation: warp w strides nodes, lane = dim (coalesced)
    int w = t >> 5, lane = t & 31;
    float a = 0.f;
    for (int i = w; i < NPER; i += 8)
        a += sc[i] * g_nf[(base + i) * D + lane];
    wacc[w][lane] = a;
    __syncthreads();
    if (t < D) {
        float acc = 0.f;
        #pragma unroll
        for (int j = 0; j < 8; j++) acc += wacc[j][t];
        out[OUT3 + b * D + t] = acc / sglob;
    }
}

// ---------------- launch ----------------
extern "C" void kernel_launch(void* const* d_in, const int* in_sizes, int n_in,
                              void* d_out, int out_size) {
    const float* feat = (const float*)d_in[0];
    const float* norm = (const float*)d_in[1];
    const float* W_w  = (const float*)d_in[2];
    const float* b_w  = (const float*)d_in[3];
    const float* W2   = (const float*)d_in[4];
    const float* b2   = (const float*)d_in[5];
    const float* attn = (const float*)d_in[6];
    const float* SL   = (const float*)d_in[7];
    const float* Wl   = (const float*)d_in[8];
    const float* bl   = (const float*)d_in[9];
    const float* zp   = (const float*)d_in[10];
    const int*   src  = (const int*)d_in[11];
    const int*   dst  = (const int*)d_in[12];
    const int*   ety  = (const int*)d_in[13];
    const int*   idx1 = (const int*)d_in[14];
    const int*   idx2 = (const int*)d_in[15];
    const int*   f2   = (const int*)d_in[16];
    const int*   tar  = (const int*)d_in[17];

    int nE     = in_sizes[11];
    int nNodes = in_sizes[0] / D;
    float* out = (float*)d_out;

    k_prep<<<1, 1024>>>(W2, b2, attn, SL, Wl);
    k_zero_acc<<<1184, 256>>>();
    k_w1<<<1184, 256>>>(feat, W_w, b_w, nNodes);
    k_edge<<<1184, 256>>>(src, dst, ety, norm, attn, nE);
    k_nf<<<1184, 256>>>(feat, bl, nNodes);
    k_zero_out<<<64, 256>>>(out);
    k_scatter<<<(nNodes + 255) / 256, 256>>>(idx2, f2, tar, out, nNodes);
    k_path<<<NBATCH, 256>>>(idx1, zp, out);
}

// round 2
// speedup vs baseline: 1.6943x; 1.6943x over previous
#include <cuda_runtime.h>

#define N_NODES 131072
#define NPER    4096
#define NBATCH  32
#define D       32
#define NREL    10
#define NG      14   // num_g_rels
#define OUT2_OFF (NBATCH * (NG + 1) * D)         // 15360
#define OUT3_OFF (OUT2_OFF + NBATCH * D)         // 16384

// ---------------- scratch (device globals; no allocation allowed) ----------------
__device__ __align__(16) float g_w1[N_NODES * D];
__device__ __align__(16) float g_U [N_NODES * D];
__device__ __align__(16) float g_V [N_NODES * D];
__device__ __align__(16) float g_S [N_NODES * 16];   // per-(node, rel) norm sums (16 pad)
__device__ __align__(16) float g_nf[N_NODES * D];
__device__ float g_M1[D * D];     // (W2a - W2b) @ W_line
__device__ float g_M2[D * D];     // W2c @ W_line
__device__ float g_M3[D * D];     // self_loop_w @ W_line
__device__ float g_Cw[NREL * D];  // (attn_r @ (W2a+W2b) + b2) @ W_line

__device__ __forceinline__ void red_add_v4(float* p, float4 v) {
    asm volatile("red.global.add.v4.f32 [%0], {%1,%2,%3,%4};"
                 :: "l"(p), "f"(v.x), "f"(v.y), "f"(v.z), "f"(v.w) : "memory");
}

// ---------------- prep: derived matrices ----------------
__global__ void k_prep(const float* __restrict__ W2, const float* __restrict__ b2,
                       const float* __restrict__ attn, const float* __restrict__ SL,
                       const float* __restrict__ Wl) {
    __shared__ float Cs[NREL * D];
    int t = threadIdx.x;
    if (t < NREL * D) {
        int r = t / D, j = t % D;
        float acc = b2[j];
        #pragma unroll
        for (int k = 0; k < D; k++)
            acc += attn[r * D + k] * (W2[k * D + j] + W2[(D + k) * D + j]);
        Cs[t] = acc;
    }
    __syncthreads();
    if (t < D * D) {
        int k = t / D, d = t % D;
        float m1 = 0.f, m2 = 0.f, m3 = 0.f;
        #pragma unroll
        for (int j = 0; j < D; j++) {
            float wl = Wl[j * D + d];
            m1 += (W2[k * D + j] - W2[(D + k) * D + j]) * wl;
            m2 += W2[(2 * D + k) * D + j] * wl;
            m3 += SL[k * D + j] * wl;
        }
        g_M1[t] = m1; g_M2[t] = m2; g_M3[t] = m3;
    }
    if (t < NREL * D) {
        int r = t / D, d = t % D;
        float acc = 0.f;
        #pragma unroll
        for (int j = 0; j < D; j++) acc += Cs[r * D + j] * Wl[j * D + d];
        g_Cw[t] = acc;
    }
}

// ---------------- init: zero accumulators + out, compute w1 ----------------
__global__ void k_init(const float* __restrict__ feat, const float* __restrict__ Ww,
                       const float* __restrict__ bw, float* __restrict__ out,
                       int n_nodes) {
    int tid = blockIdx.x * blockDim.x + threadIdx.x;
    int stride = gridDim.x * blockDim.x;
    float4 z = make_float4(0.f, 0.f, 0.f, 0.f);
    const int nUV = N_NODES * D / 4;
    for (int j = tid; j < nUV; j += stride) {
        reinterpret_cast<float4*>(g_U)[j] = z;
        reinterpret_cast<float4*>(g_V)[j] = z;
    }
    const int nS = N_NODES * 16 / 4;
    for (int j = tid; j < nS; j += stride)
        reinterpret_cast<float4*>(g_S)[j] = z;
    if (tid < OUT3_OFF) out[tid] = 0.f;

    // w1 = feat @ W_w + b_w  (warp per node, shuffle matvec)
    __shared__ float Ws[D * D];
    __shared__ float bs[D];
    for (int i = threadIdx.x; i < D * D; i += blockDim.x) Ws[i] = Ww[i];
    if (threadIdx.x < D) bs[threadIdx.x] = bw[threadIdx.x];
    __syncthreads();
    int lane = threadIdx.x & 31;
    int warp = tid >> 5;
    int nw   = stride >> 5;
    for (int n = warp; n < n_nodes; n += nw) {
        float f = feat[n * D + lane];
        float acc = bs[lane];
        #pragma unroll
        for (int k = 0; k < D; k++)
            acc += __shfl_sync(0xffffffffu, f, k) * Ws[k * D + lane];
        g_w1[n * D + lane] = acc;
    }
}

// ---------------- edge stage: 4 edges/warp, float4, vector RED ----------------
__global__ void k_edge(const int* __restrict__ src, const int* __restrict__ dst,
                       const int* __restrict__ ety, const float* __restrict__ norm,
                       const float* __restrict__ attn, int nE) {
    __shared__ float4 et_s[NREL * 8];
    for (int i = threadIdx.x; i < NREL * 8; i += blockDim.x)
        et_s[i] = reinterpret_cast<const float4*>(attn)[i];
    __syncthreads();
    int lane = threadIdx.x & 31;
    int sub  = lane & 7;       // which float4 of the 32-float row
    int grp  = lane >> 3;      // which of 4 edges in this warp
    int warp = (blockIdx.x * blockDim.x + threadIdx.x) >> 5;
    int nw   = (gridDim.x * blockDim.x) >> 5;
    for (int e0 = warp * 4; e0 < nE; e0 += nw * 4) {
        int e = e0 + grp;
        if (e >= nE) continue;
        int   s  = __ldg(&src[e]);
        int   d  = __ldg(&dst[e]);
        int   r  = __ldg(&ety[e]);
        float nm = __ldg(&norm[e]);
        float4 f = *reinterpret_cast<const float4*>(&g_w1[s * D + sub * 4]);
        float4 t1 = make_float4(nm * f.x, nm * f.y, nm * f.z, nm * f.w);
        red_add_v4(&g_U[d * D + sub * 4], t1);
        float4 et = et_s[r * 8 + sub];
        float4 v  = make_float4(t1.x * et.x, t1.y * et.y, t1.z * et.z, t1.w * et.w);
        red_add_v4(&g_V[d * D + sub * 4], v);
        if (sub == 0) atomicAdd(&g_S[d * 16 + r], nm);
    }
}

// ---------------- combine + scatter: nf = relu(U@M1 + V@M2 + feat@M3 + S@Cw + b) ----------------
__global__ void k_nf(const float* __restrict__ feat, const float* __restrict__ bline,
                     const int* __restrict__ idx1, const int* __restrict__ idx2,
                     const int* __restrict__ f2, const int* __restrict__ tar,
                     float* __restrict__ out, int n_nodes) {
    __shared__ float M1s[D * D], M2s[D * D], M3s[D * D], Cws[NREL * D], bs[D];
    for (int i = threadIdx.x; i < D * D; i += blockDim.x) {
        M1s[i] = g_M1[i]; M2s[i] = g_M2[i]; M3s[i] = g_M3[i];
    }
    for (int i = threadIdx.x; i < NREL * D; i += blockDim.x) Cws[i] = g_Cw[i];
    if (threadIdx.x < D) bs[threadIdx.x] = bline[threadIdx.x];
    __syncthreads();
    int lane = threadIdx.x & 31;
    int warp = (blockIdx.x * blockDim.x + threadIdx.x) >> 5;
    int nw   = (gridDim.x * blockDim.x) >> 5;
    for (int n = warp; n < n_nodes; n += nw) {
        int i1 = __ldg(&idx1[n]);
        int i2 = __ldg(&idx2[n]);
        int tr = __ldg(&tar[n]);
        if (i1 != 1 && i2 == 0 && tr != 1) continue;   // node feeds no output
        float u = g_U[n * D + lane];
        float v = g_V[n * D + lane];
        float f = feat[n * D + lane];
        float sv = (lane < 16) ? g_S[n * 16 + lane] : 0.f;
        float acc = bs[lane];
        #pragma unroll
        for (int r = 0; r < NREL; r++)
            acc += __shfl_sync(0xffffffffu, sv, r) * Cws[r * D + lane];
        #pragma unroll
        for (int k = 0; k < D; k++) {
            acc += __shfl_sync(0xffffffffu, u, k) * M1s[k * D + lane];
            acc += __shfl_sync(0xffffffffu, v, k) * M2s[k * D + lane];
            acc += __shfl_sync(0xffffffffu, f, k) * M3s[k * D + lane];
        }
        float val = fmaxf(acc, 0.f);
        int b = n / NPER;
        if (i1 == 1) g_nf[n * D + lane] = val;
        if (i2 != 0) {
            int slot = __ldg(&f2[n]) + 1;              // index_offset = 1
            if (slot <= NG)                            // slot NG+1 = dump row (dropped)
                out[(b * (NG + 1) + slot) * D + lane] = val;
        }
        if (tr == 1) atomicAdd(&out[OUT2_OFF + b * D + lane], val);
    }
}

// ---------------- per-batch path softmax aggregation ----------------
__global__ void k_path(const int* __restrict__ idx1, const float* __restrict__ zero_path,
                       float* __restrict__ out) {
    __shared__ float sc[NPER];
    __shared__ float tgt[D];
    __shared__ float red[16];
    __shared__ float wacc[16][D];
    int b = blockIdx.x;
    int t = threadIdx.x;
    int w = t >> 5, lane = t & 31;
    if (t < D) tgt[t] = out[OUT2_OFF + b * D + t];
    __syncthreads();
    size_t base = (size_t)b * NPER;

    // scores (float4 row loads)
    for (int i = t; i < NPER; i += 512) {
        float s = -1e30f;
        if (idx1[base + i] == 1) {
            const float4* row = reinterpret_cast<const float4*>(g_nf + (base + i) * D);
            float acc = 0.f;
            #pragma unroll
            for (int k = 0; k < 8; k++) {
                float4 r4 = row[k];
                acc += r4.x * tgt[k * 4 + 0] + r4.y * tgt[k * 4 + 1]
                     + r4.z * tgt[k * 4 + 2] + r4.w * tgt[k * 4 + 3];
            }
            s = acc;
        }
        sc[i] = s;
    }
    __syncthreads();

    // block max (warp shuffle + smem)
    float m = -1e30f;
    for (int i = t; i < NPER; i += 512) m = fmaxf(m, sc[i]);
    #pragma unroll
    for (int off = 16; off > 0; off >>= 1)
        m = fmaxf(m, __shfl_xor_sync(0xffffffffu, m, off));
    if (lane == 0) red[w] = m;
    __syncthreads();
    if (t < 16) {
        float mm = red[t];
        #pragma unroll
        for (int off = 8; off > 0; off >>= 1)
            mm = fmaxf(mm, __shfl_xor_sync(0xffffu, mm, off));
        red[t] = mm;
    }
    __syncthreads();
    float mglob = red[0];
    __syncthreads();

    if (mglob < -1e29f) {                        // no path nodes -> zero_path
        if (t < D) out[OUT3_OFF + b * D + t] = zero_path[t];
        return;
    }

    // exp + sum
    float ssum = 0.f;
    for (int i = t; i < NPER; i += 512) {
        float e = (sc[i] > -1e29f) ? __expf(sc[i] - mglob) : 0.f;
        sc[i] = e;
        ssum += e;
    }
    #pragma unroll
    for (int off = 16; off > 0; off >>= 1)
        ssum += __shfl_xor_sync(0xffffffffu, ssum, off);
    if (lane == 0) red[w] = ssum;
    __syncthreads();
    if (t < 16) {
        float s2 = red[t];
        #pragma unroll
        for (int off = 8; off > 0; off >>= 1)
            s2 += __shfl_xor_sync(0xffffu, s2, off);
        red[t] = s2;
    }
    __syncthreads();
    float sglob = red[0];

    // weighted aggregation: 16 warps stride rows, lane = dim; skip zero-alpha rows
    float a = 0.f;
    for (int i = w; i < NPER; i += 16) {
        float e = sc[i];
        if (e == 0.f) continue;                  // warp-uniform branch
        a += e * g_nf[(base + i) * D + lane];
    }
    wacc[w][lane] = a;
    __syncthreads();
    if (t < D) {
        float acc = 0.f;
        #pragma unroll
        for (int j = 0; j < 16; j++) acc += wacc[j][t];
        out[OUT3_OFF + b * D + t] = acc / sglob;
    }
}

// ---------------- launch ----------------
extern "C" void kernel_launch(void* const* d_in, const int* in_sizes, int n_in,
                              void* d_out, int out_size) {
    const float* feat = (const float*)d_in[0];
    const float* norm = (const float*)d_in[1];
    const float* W_w  = (const float*)d_in[2];
    const float* b_w  = (const float*)d_in[3];
    const float* W2   = (const float*)d_in[4];
    const float* b2   = (const float*)d_in[5];
    const float* attn = (const float*)d_in[6];
    const float* SL   = (const float*)d_in[7];
    const float* Wl   = (const float*)d_in[8];
    const float* bl   = (const float*)d_in[9];
    const float* zp   = (const float*)d_in[10];
    const int*   src  = (const int*)d_in[11];
    const int*   dst  = (const int*)d_in[12];
    const int*   ety  = (const int*)d_in[13];
    const int*   idx1 = (const int*)d_in[14];
    const int*   idx2 = (const int*)d_in[15];
    const int*   f2   = (const int*)d_in[16];
    const int*   tar  = (const int*)d_in[17];

    int nE     = in_sizes[11];
    int nNodes = in_sizes[0] / D;
    float* out = (float*)d_out;

    k_prep<<<1, 1024>>>(W2, b2, attn, SL, Wl);
    k_init<<<1184, 256>>>(feat, W_w, b_w, out, nNodes);
    k_edge<<<1184, 256>>>(src, dst, ety, norm, attn, nE);
    k_nf  <<<1184, 256>>>(feat, bl, idx1, idx2, f2, tar, out, nNodes);
    k_path<<<NBATCH, 512>>>(idx1, zp, out);
}

// round 3
// speedup vs baseline: 2.1438x; 1.2653x over previous
#include <cuda_runtime.h>

#define N_NODES 131072
#define NPER    4096
#define NBATCH  32
#define D       32
#define NREL    10
#define NG      14   // num_g_rels
#define OUT2_OFF (NBATCH * (NG + 1) * D)         // 15360
#define OUT3_OFF (OUT2_OFF + NBATCH * D)         // 16384

// ---------------- scratch (device globals; no allocation allowed) ----------------
__device__ __align__(16) float g_w1[N_NODES * D];
__device__ __align__(16) float g_U [N_NODES * D];
__device__ __align__(16) float g_V [N_NODES * D];
__device__ __align__(16) float g_S [N_NODES * 16];   // per-(node, rel) norm sums (16 pad)
__device__ __align__(16) float g_nf[N_NODES * D];
__device__ int   g_list[N_NODES];                    // compacted active-node indices
__device__ int   g_cnt;
__device__ float g_M1[D * D];     // (W2a - W2b) @ W_line
__device__ float g_M2[D * D];     // W2c @ W_line
__device__ float g_M3[D * D];     // self_loop_w @ W_line
__device__ float g_Cw[NREL * D];  // (attn_r @ (W2a+W2b) + b2) @ W_line

__device__ __forceinline__ void red_add_v4(float* p, float4 v) {
    asm volatile("red.global.add.v4.f32 [%0], {%1,%2,%3,%4};"
                 :: "l"(p), "f"(v.x), "f"(v.y), "f"(v.z), "f"(v.w) : "memory");
}
__device__ __forceinline__ float fsel(const float4& q, int c) {
    // c is a compile-time constant after full unroll
    return c == 0 ? q.x : (c == 1 ? q.y : (c == 2 ? q.z : q.w));
}

// ---------------- prep: derived matrices + counter reset ----------------
__global__ void k_prep(const float* __restrict__ W2, const float* __restrict__ b2,
                       const float* __restrict__ attn, const float* __restrict__ SL,
                       const float* __restrict__ Wl) {
    __shared__ float Cs[NREL * D];
    int t = threadIdx.x;
    if (t == 0) g_cnt = 0;
    if (t < NREL * D) {
        int r = t / D, j = t % D;
        float acc = b2[j];
        #pragma unroll
        for (int k = 0; k < D; k++)
            acc += attn[r * D + k] * (W2[k * D + j] + W2[(D + k) * D + j]);
        Cs[t] = acc;
    }
    __syncthreads();
    if (t < D * D) {
        int k = t / D, d = t % D;
        float m1 = 0.f, m2 = 0.f, m3 = 0.f;
        #pragma unroll
        for (int j = 0; j < D; j++) {
            float wl = Wl[j * D + d];
            m1 += (W2[k * D + j] - W2[(D + k) * D + j]) * wl;
            m2 += W2[(2 * D + k) * D + j] * wl;
            m3 += SL[k * D + j] * wl;
        }
        g_M1[t] = m1; g_M2[t] = m2; g_M3[t] = m3;
    }
    if (t < NREL * D) {
        int r = t / D, d = t % D;
        float acc = 0.f;
        #pragma unroll
        for (int j = 0; j < D; j++) acc += Cs[r * D + j] * Wl[j * D + d];
        g_Cw[t] = acc;
    }
}

// ---------------- init: zero acc + out, w1 matvec (4 nodes/warp), compaction ----------------
__global__ void k_init(const float* __restrict__ feat, const float* __restrict__ Ww,
                       const float* __restrict__ bw, float* __restrict__ out,
                       const int* __restrict__ idx1, const int* __restrict__ idx2,
                       const int* __restrict__ tar, int n_nodes) {
    int tid = blockIdx.x * blockDim.x + threadIdx.x;
    int stride = gridDim.x * blockDim.x;
    float4 z = make_float4(0.f, 0.f, 0.f, 0.f);
    const int nUV = N_NODES * D / 4;
    for (int j = tid; j < nUV; j += stride) {
        reinterpret_cast<float4*>(g_U)[j] = z;
        reinterpret_cast<float4*>(g_V)[j] = z;
    }
    const int nS = N_NODES * 16 / 4;
    for (int j = tid; j < nS; j += stride)
        reinterpret_cast<float4*>(g_S)[j] = z;
    if (tid < OUT3_OFF) out[tid] = 0.f;

    // active-node compaction (warp-aggregated)
    {
        int n = tid;                              // stride >= n_nodes
        bool active = false;
        if (n < n_nodes)
            active = (__ldg(&idx1[n]) == 1) || (__ldg(&idx2[n]) != 0) || (__ldg(&tar[n]) == 1);
        unsigned m = __ballot_sync(0xffffffffu, active);
        if (m) {
            int lane = threadIdx.x & 31;
            int rank = __popc(m & ((1u << lane) - 1u));
            int base = 0;
            if (lane == __ffs(m) - 1) base = atomicAdd(&g_cnt, __popc(m));
            base = __shfl_sync(0xffffffffu, base, __ffs(m) - 1);
            if (active) g_list[base + rank] = n;
        }
    }

    // w1 = feat @ W_w + b_w : 4 nodes per warp, 8 lanes x float4 per node
    __shared__ __align__(16) float Ws[D * D];
    for (int i = threadIdx.x; i < D * D; i += blockDim.x) Ws[i] = Ww[i];
    __syncthreads();
    const float4* Ws4 = reinterpret_cast<const float4*>(Ws);
    int lane = threadIdx.x & 31;
    int sub  = lane & 7;
    int grp  = lane >> 3;
    int warp = tid >> 5;
    int nw   = stride >> 5;
    float4 b4 = __ldg(reinterpret_cast<const float4*>(bw) + sub);
    for (int base = warp * 4; base < n_nodes; base += nw * 4) {
        int n = base + grp;                       // n_nodes % 4 == 0 -> always valid
        float4 f4 = *reinterpret_cast<const float4*>(&feat[n * D + sub * 4]);
        float4 acc = b4;
        #pragma unroll
        for (int k = 0; k < D; k++) {
            float fk = __shfl_sync(0xffffffffu, fsel(f4, k & 3), k >> 2, 8);
            float4 w = Ws4[k * 8 + sub];
            acc.x += fk * w.x; acc.y += fk * w.y; acc.z += fk * w.z; acc.w += fk * w.w;
        }
        *reinterpret_cast<float4*>(&g_w1[n * D + sub * 4]) = acc;
    }
}

// ---------------- edge stage: 4 edges/warp, float4, vector RED, unroll 2 ----------------
__global__ void k_edge(const int* __restrict__ src, const int* __restrict__ dst,
                       const int* __restrict__ ety, const float* __restrict__ norm,
                       const float* __restrict__ attn, int nE) {
    __shared__ float4 et_s[NREL * 8];
    for (int i = threadIdx.x; i < NREL * 8; i += blockDim.x)
        et_s[i] = reinterpret_cast<const float4*>(attn)[i];
    __syncthreads();
    int lane = threadIdx.x & 31;
    int sub  = lane & 7;
    int grp  = lane >> 3;
    int warp = (blockIdx.x * blockDim.x + threadIdx.x) >> 5;
    int nw   = (gridDim.x * blockDim.x) >> 5;
    for (int e0 = warp * 8; e0 < nE; e0 += nw * 8) {
        #pragma unroll
        for (int u = 0; u < 2; u++) {
            int e = e0 + u * 4 + grp;
            if (e >= nE) continue;
            int   s  = __ldg(&src[e]);
            int   d  = __ldg(&dst[e]);
            int   r  = __ldg(&ety[e]);
            float nm = __ldg(&norm[e]);
            float4 f = *reinterpret_cast<const float4*>(&g_w1[s * D + sub * 4]);
            float4 t1 = make_float4(nm * f.x, nm * f.y, nm * f.z, nm * f.w);
            red_add_v4(&g_U[d * D + sub * 4], t1);
            float4 et = et_s[r * 8 + sub];
            float4 v  = make_float4(t1.x * et.x, t1.y * et.y, t1.z * et.z, t1.w * et.w);
            red_add_v4(&g_V[d * D + sub * 4], v);
            if (sub == 0) atomicAdd(&g_S[d * 16 + r], nm);
        }
    }
}

// ---------------- combine + scatter over compacted list: 4 nodes/warp ----------------
__global__ void k_nf(const float* __restrict__ feat, const float* __restrict__ bline,
                     const int* __restrict__ idx1, const int* __restrict__ idx2,
                     const int* __restrict__ f2, const int* __restrict__ tar,
                     float* __restrict__ out) {
    __shared__ __align__(16) float M1s[D * D], M2s[D * D], M3s[D * D], Cws[NREL * D];
    for (int i = threadIdx.x; i < D * D; i += blockDim.x) {
        M1s[i] = g_M1[i]; M2s[i] = g_M2[i]; M3s[i] = g_M3[i];
    }
    for (int i = threadIdx.x; i < NREL * D; i += blockDim.x) Cws[i] = g_Cw[i];
    __syncthreads();
    const float4* M14 = reinterpret_cast<const float4*>(M1s);
    const float4* M24 = reinterpret_cast<const float4*>(M2s);
    const float4* M34 = reinterpret_cast<const float4*>(M3s);
    const float4* Cw4 = reinterpret_cast<const float4*>(Cws);
    int cnt  = g_cnt;
    int lane = threadIdx.x & 31;
    int sub  = lane & 7;
    int grp  = lane >> 3;
    int warp = (blockIdx.x * blockDim.x + threadIdx.x) >> 5;
    int nw   = (gridDim.x * blockDim.x) >> 5;
    float4 b4 = __ldg(reinterpret_cast<const float4*>(bline) + sub);

    for (int base = warp * 4; base < cnt; base += nw * 4) {
        int i = base + grp;
        bool valid = i < cnt;
        int n = g_list[valid ? i : 0];

        float4 u4 = *reinterpret_cast<const float4*>(&g_U[n * D + sub * 4]);
        float4 v4 = *reinterpret_cast<const float4*>(&g_V[n * D + sub * 4]);
        float4 f4 = *reinterpret_cast<const float4*>(&feat[n * D + sub * 4]);
        float sv0 = g_S[n * 16 + sub];
        float sv1 = g_S[n * 16 + 8 + sub];

        float4 acc = b4;
        #pragma unroll
        for (int r = 0; r < NREL; r++) {
            float s_r = __shfl_sync(0xffffffffu, r < 8 ? sv0 : sv1, r & 7, 8);
            float4 c = Cw4[r * 8 + sub];
            acc.x += s_r * c.x; acc.y += s_r * c.y; acc.z += s_r * c.z; acc.w += s_r * c.w;
        }
        #pragma unroll
        for (int k = 0; k < D; k++) {
            float uk = __shfl_sync(0xffffffffu, fsel(u4, k & 3), k >> 2, 8);
            float vk = __shfl_sync(0xffffffffu, fsel(v4, k & 3), k >> 2, 8);
            float fk = __shfl_sync(0xffffffffu, fsel(f4, k & 3), k >> 2, 8);
            float4 m1 = M14[k * 8 + sub];
            float4 m2 = M24[k * 8 + sub];
            float4 m3 = M34[k * 8 + sub];
            acc.x += uk * m1.x + vk * m2.x + fk * m3.x;
            acc.y += uk * m1.y + vk * m2.y + fk * m3.y;
            acc.z += uk * m1.z + vk * m2.z + fk * m3.z;
            acc.w += uk * m1.w + vk * m2.w + fk * m3.w;
        }
        float4 val = make_float4(fmaxf(acc.x, 0.f), fmaxf(acc.y, 0.f),
                                 fmaxf(acc.z, 0.f), fmaxf(acc.w, 0.f));
        if (valid) {
            int b  = n >> 12;                     // n / NPER
            int i1 = __ldg(&idx1[n]);
            int i2 = __ldg(&idx2[n]);
            int tr = __ldg(&tar[n]);
            if (i1 == 1)
                *reinterpret_cast<float4*>(&g_nf[n * D + sub * 4]) = val;
            if (i2 != 0) {
                int slot = __ldg(&f2[n]) + 1;     // index_offset = 1
                if (slot <= NG)                   // slot NG+1 = dump row (dropped)
                    *reinterpret_cast<float4*>(&out[(b * (NG + 1) + slot) * D + sub * 4]) = val;
            }
            if (tr == 1)
                red_add_v4(&out[OUT2_OFF + b * D + sub * 4], val);
        }
    }
}

// ---------------- per-batch path softmax aggregation ----------------
__global__ void k_path(const int* __restrict__ idx1, const float* __restrict__ zero_path,
                       float* __restrict__ out) {
    __shared__ float sc[NPER];
    __shared__ float tgt[D];
    __shared__ float red[16];
    __shared__ float wacc[16][D];
    int b = blockIdx.x;
    int t = threadIdx.x;
    int w = t >> 5, lane = t & 31;
    if (t < D) tgt[t] = out[OUT2_OFF + b * D + t];
    __syncthreads();
    size_t base = (size_t)b * NPER;

    for (int i = t; i < NPER; i += 512) {
        float s = -1e30f;
        if (idx1[base + i] == 1) {
            const float4* row = reinterpret_cast<const float4*>(g_nf + (base + i) * D);
            float acc = 0.f;
            #pragma unroll
            for (int k = 0; k < 8; k++) {
                float4 r4 = row[k];
                acc += r4.x * tgt[k * 4 + 0] + r4.y * tgt[k * 4 + 1]
                     + r4.z * tgt[k * 4 + 2] + r4.w * tgt[k * 4 + 3];
            }
            s = acc;
        }
        sc[i] = s;
    }
    __syncthreads();

    float m = -1e30f;
    for (int i = t; i < NPER; i += 512) m = fmaxf(m, sc[i]);
    #pragma unroll
    for (int off = 16; off > 0; off >>= 1)
        m = fmaxf(m, __shfl_xor_sync(0xffffffffu, m, off));
    if (lane == 0) red[w] = m;
    __syncthreads();
    if (t < 16) {
        float mm = red[t];
        #pragma unroll
        for (int off = 8; off > 0; off >>= 1)
            mm = fmaxf(mm, __shfl_xor_sync(0xffffu, mm, off));
        red[t] = mm;
    }
    __syncthreads();
    float mglob = red[0];
    __syncthreads();

    if (mglob < -1e29f) {
        if (t < D) out[OUT3_OFF + b * D + t] = zero_path[t];
        return;
    }

    float ssum = 0.f;
    for (int i = t; i < NPER; i += 512) {
        float e = (sc[i] > -1e29f) ? __expf(sc[i] - mglob) : 0.f;
        sc[i] = e;
        ssum += e;
    }
    #pragma unroll
    for (int off = 16; off > 0; off >>= 1)
        ssum += __shfl_xor_sync(0xffffffffu, ssum, off);
    if (lane == 0) red[w] = ssum;
    __syncthreads();
    if (t < 16) {
        float s2 = red[t];
        #pragma unroll
        for (int off = 8; off > 0; off >>= 1)
            s2 += __shfl_xor_sync(0xffffu, s2, off);
        red[t] = s2;
    }
    __syncthreads();
    float sglob = red[0];

    float a = 0.f;
    for (int i = w; i < NPER; i += 16) {
        float e = sc[i];
        if (e == 0.f) continue;
        a += e * g_nf[(base + i) * D + lane];
    }
    wacc[w][lane] = a;
    __syncthreads();
    if (t < D) {
        float acc = 0.f;
        #pragma unroll
        for (int j = 0; j < 16; j++) acc += wacc[j][t];
        out[OUT3_OFF + b * D + t] = acc / sglob;
    }
}

// ---------------- launch ----------------
extern "C" void kernel_launch(void* const* d_in, const int* in_sizes, int n_in,
                              void* d_out, int out_size) {
    const float* feat = (const float*)d_in[0];
    const float* norm = (const float*)d_in[1];
    const float* W_w  = (const float*)d_in[2];
    const float* b_w  = (const float*)d_in[3];
    const float* W2   = (const float*)d_in[4];
    const float* b2   = (const float*)d_in[5];
    const float* attn = (const float*)d_in[6];
    const float* SL   = (const float*)d_in[7];
    const float* Wl   = (const float*)d_in[8];
    const float* bl   = (const float*)d_in[9];
    const float* zp   = (const float*)d_in[10];
    const int*   src  = (const int*)d_in[11];
    const int*   dst  = (const int*)d_in[12];
    const int*   ety  = (const int*)d_in[13];
    const int*   idx1 = (const int*)d_in[14];
    const int*   idx2 = (const int*)d_in[15];
    const int*   f2   = (const int*)d_in[16];
    const int*   tar  = (const int*)d_in[17];

    int nE     = in_sizes[11];
    int nNodes = in_sizes[0] / D;
    float* out = (float*)d_out;

    k_prep<<<1, 1024>>>(W2, b2, attn, SL, Wl);
    k_init<<<1184, 256>>>(feat, W_w, b_w, out, idx1, idx2, tar, nNodes);
    k_edge<<<1184, 256>>>(src, dst, ety, norm, attn, nE);
    k_nf  <<<1184, 256>>>(feat, bl, idx1, idx2, f2, tar, out);
    k_path<<<NBATCH, 512>>>(idx1, zp, out);
}

// round 4
// speedup vs baseline: 2.6990x; 1.2590x over previous
#include <cuda_runtime.h>

#define N_NODES 131072
#define NPER    4096
#define NBATCH  32
#define D       32
#define NREL    10
#define NG      14   // num_g_rels
#define SPLIT   8    // path sub-blocks per batch
#define OUT2_OFF (NBATCH * (NG + 1) * D)         // 15360
#define OUT3_OFF (OUT2_OFF + NBATCH * D)         // 16384

// ---------------- scratch (device globals; no allocation allowed) ----------------
__device__ __align__(16) float g_w1[N_NODES * D];
__device__ __align__(16) float g_U [N_NODES * D];
__device__ __align__(16) float g_V [N_NODES * D];
__device__ __align__(16) float g_S [N_NODES * 16];   // per-(node, rel) norm sums (16 pad)
__device__ __align__(16) float g_nf[N_NODES * D];
__device__ int   g_list[N_NODES];                    // compacted active-node indices
__device__ int   g_cnt;                              // invariant: 0 at kernel_launch entry
__device__ float g_M1[D * D];     // (W2a - W2b) @ W_line
__device__ float g_M2[D * D];     // W2c @ W_line
__device__ float g_M3[D * D];     // self_loop_w @ W_line
__device__ float g_Cw[NREL * D];  // (attn_r @ (W2a+W2b) + b2) @ W_line
__device__ float g_pm[NBATCH * SPLIT];
__device__ float g_ps[NBATCH * SPLIT];
__device__ __align__(16) float g_pv[NBATCH * SPLIT * D];

__device__ __forceinline__ void red_add_v4(float* p, float4 v) {
    asm volatile("red.global.add.v4.f32 [%0], {%1,%2,%3,%4};"
                 :: "l"(p), "f"(v.x), "f"(v.y), "f"(v.z), "f"(v.w) : "memory");
}
__device__ __forceinline__ float fsel(const float4& q, int c) {
    return c == 0 ? q.x : (c == 1 ? q.y : (c == 2 ? q.z : q.w));
}

// ---------------- init: prep (block 0) + zero + compaction + w1 (16 nodes/warp) ----------------
__global__ void k_init(const float* __restrict__ feat, const float* __restrict__ Ww,
                       const float* __restrict__ bw,
                       const float* __restrict__ W2, const float* __restrict__ b2,
                       const float* __restrict__ attn, const float* __restrict__ SL,
                       const float* __restrict__ Wl,
                       float* __restrict__ out,
                       const int* __restrict__ idx1, const int* __restrict__ idx2,
                       const int* __restrict__ tar, int n_nodes) {
    // ---- prep (block 0 only): derived matrices ----
    if (blockIdx.x == 0) {
        __shared__ float Cs[NREL * D];
        int t = threadIdx.x;
        for (int i = t; i < NREL * D; i += blockDim.x) {
            int r = i / D, j = i % D;
            float acc = b2[j];
            #pragma unroll
            for (int k = 0; k < D; k++)
                acc += attn[r * D + k] * (W2[k * D + j] + W2[(D + k) * D + j]);
            Cs[i] = acc;
        }
        __syncthreads();
        for (int i = t; i < D * D; i += blockDim.x) {
            int k = i / D, d = i % D;
            float m1 = 0.f, m2 = 0.f, m3 = 0.f;
            #pragma unroll
            for (int j = 0; j < D; j++) {
                float wl = Wl[j * D + d];
                m1 += (W2[k * D + j] - W2[(D + k) * D + j]) * wl;
                m2 += W2[(2 * D + k) * D + j] * wl;
                m3 += SL[k * D + j] * wl;
            }
            g_M1[i] = m1; g_M2[i] = m2; g_M3[i] = m3;
        }
        for (int i = t; i < NREL * D; i += blockDim.x) {
            int r = i / D, d = i % D;
            float acc = 0.f;
            #pragma unroll
            for (int j = 0; j < D; j++) acc += Cs[r * D + j] * Wl[j * D + d];
            g_Cw[i] = acc;
        }
    }

    int tid = blockIdx.x * blockDim.x + threadIdx.x;
    int stride = gridDim.x * blockDim.x;
    float4 z = make_float4(0.f, 0.f, 0.f, 0.f);
    const int nUV = N_NODES * D / 4;
    for (int j = tid; j < nUV; j += stride) {
        reinterpret_cast<float4*>(g_U)[j] = z;
        reinterpret_cast<float4*>(g_V)[j] = z;
    }
    const int nS = N_NODES * 16 / 4;
    for (int j = tid; j < nS; j += stride)
        reinterpret_cast<float4*>(g_S)[j] = z;
    if (tid < OUT3_OFF) out[tid] = 0.f;

    // ---- active-node compaction (warp-aggregated; g_cnt == 0 at entry) ----
    {
        int n = tid;                              // stride >= n_nodes
        bool active = false;
        if (n < n_nodes)
            active = (__ldg(&idx1[n]) == 1) || (__ldg(&idx2[n]) != 0) || (__ldg(&tar[n]) == 1);
        unsigned m = __ballot_sync(0xffffffffu, active);
        if (m) {
            int lane = threadIdx.x & 31;
            int rank = __popc(m & ((1u << lane) - 1u));
            int base = 0;
            if (lane == __ffs(m) - 1) base = atomicAdd(&g_cnt, __popc(m));
            base = __shfl_sync(0xffffffffu, base, __ffs(m) - 1);
            if (active) g_list[base + rank] = n;
        }
    }

    // ---- w1 = feat @ W_w + b_w : 16 nodes/warp (4 per 8-lane group) ----
    __shared__ __align__(16) float Ws[D * D];
    for (int i = threadIdx.x; i < D * D; i += blockDim.x) Ws[i] = Ww[i];
    __syncthreads();
    const float4* Ws4 = reinterpret_cast<const float4*>(Ws);
    int lane = threadIdx.x & 31;
    int sub  = lane & 7;
    int grp  = lane >> 3;
    int warp = tid >> 5;
    int nw   = stride >> 5;
    float4 b4 = __ldg(reinterpret_cast<const float4*>(bw) + sub);
    for (int base = warp * 16; base < n_nodes; base += nw * 16) {
        float4 f4[4], acc[4];
        #pragma unroll
        for (int t = 0; t < 4; t++) {
            int n = base + grp * 4 + t;           // n_nodes % 16 == 0
            f4[t]  = *reinterpret_cast<const float4*>(&feat[n * D + sub * 4]);
            acc[t] = b4;
        }
        #pragma unroll
        for (int k = 0; k < D; k++) {
            float4 w = Ws4[k * 8 + sub];
            #pragma unroll
            for (int t = 0; t < 4; t++) {
                float fk = __shfl_sync(0xffffffffu, fsel(f4[t], k & 3), k >> 2, 8);
                acc[t].x += fk * w.x; acc[t].y += fk * w.y;
                acc[t].z += fk * w.z; acc[t].w += fk * w.w;
            }
        }
        #pragma unroll
        for (int t = 0; t < 4; t++) {
            int n = base + grp * 4 + t;
            *reinterpret_cast<float4*>(&g_w1[n * D + sub * 4]) = acc[t];
        }
    }
}

// ---------------- edge stage: 4 edges/warp, float4, vector RED, unroll 2 ----------------
__global__ void k_edge(const int* __restrict__ src, const int* __restrict__ dst,
                       const int* __restrict__ ety, const float* __restrict__ norm,
                       const float* __restrict__ attn, int nE) {
    __shared__ float4 et_s[NREL * 8];
    for (int i = threadIdx.x; i < NREL * 8; i += blockDim.x)
        et_s[i] = reinterpret_cast<const float4*>(attn)[i];
    __syncthreads();
    int lane = threadIdx.x & 31;
    int sub  = lane & 7;
    int grp  = lane >> 3;
    int warp = (blockIdx.x * blockDim.x + threadIdx.x) >> 5;
    int nw   = (gridDim.x * blockDim.x) >> 5;
    for (int e0 = warp * 8; e0 < nE; e0 += nw * 8) {
        #pragma unroll
        for (int u = 0; u < 2; u++) {
            int e = e0 + u * 4 + grp;
            if (e >= nE) continue;
            int   s  = __ldg(&src[e]);
            int   d  = __ldg(&dst[e]);
            int   r  = __ldg(&ety[e]);
            float nm = __ldg(&norm[e]);
            float4 f = *reinterpret_cast<const float4*>(&g_w1[s * D + sub * 4]);
            float4 t1 = make_float4(nm * f.x, nm * f.y, nm * f.z, nm * f.w);
            red_add_v4(&g_U[d * D + sub * 4], t1);
            float4 et = et_s[r * 8 + sub];
            float4 v  = make_float4(t1.x * et.x, t1.y * et.y, t1.z * et.z, t1.w * et.w);
            red_add_v4(&g_V[d * D + sub * 4], v);
            if (sub == 0) atomicAdd(&g_S[d * 16 + r], nm);
        }
    }
}

// ---------------- combine + scatter over compacted list: 16 nodes/warp ----------------
__global__ void __launch_bounds__(256, 2)
k_nf(const float* __restrict__ feat, const float* __restrict__ bline,
     const int* __restrict__ idx1, const int* __restrict__ idx2,
     const int* __restrict__ f2, const int* __restrict__ tar,
     float* __restrict__ out) {
    __shared__ __align__(16) float M1s[D * D], M2s[D * D], M3s[D * D], Cws[NREL * D];
    for (int i = threadIdx.x; i < D * D; i += blockDim.x) {
        M1s[i] = g_M1[i]; M2s[i] = g_M2[i]; M3s[i] = g_M3[i];
    }
    for (int i = threadIdx.x; i < NREL * D; i += blockDim.x) Cws[i] = g_Cw[i];
    __syncthreads();
    const float4* M14 = reinterpret_cast<const float4*>(M1s);
    const float4* M24 = reinterpret_cast<const float4*>(M2s);
    const float4* M34 = reinterpret_cast<const float4*>(M3s);
    const float4* Cw4 = reinterpret_cast<const float4*>(Cws);
    int cnt  = g_cnt;
    int lane = threadIdx.x & 31;
    int sub  = lane & 7;
    int grp  = lane >> 3;
    int warp = (blockIdx.x * blockDim.x + threadIdx.x) >> 5;
    int nw   = (gridDim.x * blockDim.x) >> 5;
    float4 b4 = __ldg(reinterpret_cast<const float4*>(bline) + sub);

    for (int base = warp * 16; base < cnt; base += nw * 16) {
        int  n_t[4];
        bool val_t[4];
        float4 acc[4];
        #pragma unroll
        for (int t = 0; t < 4; t++) {
            int i = base + grp * 4 + t;
            val_t[t] = i < cnt;
            n_t[t] = g_list[val_t[t] ? i : 0];
            acc[t] = b4;
        }
        // relation (S @ Cw) phase
        {
            float sv0[4], sv1[4];
            #pragma unroll
            for (int t = 0; t < 4; t++) {
                sv0[t] = g_S[n_t[t] * 16 + sub];
                sv1[t] = g_S[n_t[t] * 16 + 8 + sub];
            }
            #pragma unroll
            for (int r = 0; r < NREL; r++) {
                float4 c = Cw4[r * 8 + sub];
                #pragma unroll
                for (int t = 0; t < 4; t++) {
                    float s_r = __shfl_sync(0xffffffffu, r < 8 ? sv0[t] : sv1[t], r & 7, 8);
                    acc[t].x += s_r * c.x; acc[t].y += s_r * c.y;
                    acc[t].z += s_r * c.z; acc[t].w += s_r * c.w;
                }
            }
        }
        // main U/V/feat matvec phase
        {
            float4 u4[4], v4[4], f4[4];
            #pragma unroll
            for (int t = 0; t < 4; t++) {
                u4[t] = *reinterpret_cast<const float4*>(&g_U[n_t[t] * D + sub * 4]);
                v4[t] = *reinterpret_cast<const float4*>(&g_V[n_t[t] * D + sub * 4]);
                f4[t] = *reinterpret_cast<const float4*>(&feat[n_t[t] * D + sub * 4]);
            }
            #pragma unroll
            for (int k = 0; k < D; k++) {
                float4 m1 = M14[k * 8 + sub];
                float4 m2 = M24[k * 8 + sub];
                float4 m3 = M34[k * 8 + sub];
                #pragma unroll
                for (int t = 0; t < 4; t++) {
                    float uk = __shfl_sync(0xffffffffu, fsel(u4[t], k & 3), k >> 2, 8);
                    float vk = __shfl_sync(0xffffffffu, fsel(v4[t], k & 3), k >> 2, 8);
                    float fk = __shfl_sync(0xffffffffu, fsel(f4[t], k & 3), k >> 2, 8);
                    acc[t].x += uk * m1.x + vk * m2.x + fk * m3.x;
                    acc[t].y += uk * m1.y + vk * m2.y + fk * m3.y;
                    acc[t].z += uk * m1.z + vk * m2.z + fk * m3.z;
                    acc[t].w += uk * m1.w + vk * m2.w + fk * m3.w;
                }
            }
        }
        // epilogue
        #pragma unroll
        for (int t = 0; t < 4; t++) {
            if (!val_t[t]) continue;
            int n = n_t[t];
            float4 val = make_float4(fmaxf(acc[t].x, 0.f), fmaxf(acc[t].y, 0.f),
                                     fmaxf(acc[t].z, 0.f), fmaxf(acc[t].w, 0.f));
            int b  = n >> 12;                     // n / NPER
            int i1 = __ldg(&idx1[n]);
            int i2 = __ldg(&idx2[n]);
            int tr = __ldg(&tar[n]);
            if (i1 == 1)
                *reinterpret_cast<float4*>(&g_nf[n * D + sub * 4]) = val;
            if (i2 != 0) {
                int slot = __ldg(&f2[n]) + 1;     // index_offset = 1
                if (slot <= NG)                   // slot NG+1 = dump row (dropped)
                    *reinterpret_cast<float4*>(&out[(b * (NG + 1) + slot) * D + sub * 4]) = val;
            }
            if (tr == 1)
                red_add_v4(&out[OUT2_OFF + b * D + sub * 4], val);
        }
    }
}

// ---------------- path softmax phase A: per-sub-block max/sum/partial ----------------
__global__ void k_path1(const int* __restrict__ idx1, const float* __restrict__ out) {
    const int R = NPER / SPLIT;                   // 512 rows per block
    __shared__ float sc[R];
    __shared__ float tgt[D];
    __shared__ float red[8];
    __shared__ float wacc[8][D];
    int b = blockIdx.x / SPLIT, j = blockIdx.x % SPLIT;
    int t = threadIdx.x;
    int w = t >> 5, lane = t & 31;
    if (t < D) tgt[t] = out[OUT2_OFF + b * D + t];
    __syncthreads();
    size_t rbase = (size_t)b * NPER + j * R;

    // scores
    for (int i = t; i < R; i += 256) {
        float s = -1e30f;
        if (idx1[rbase + i] == 1) {
            const float4* row = reinterpret_cast<const float4*>(g_nf + (rbase + i) * D);
            float acc = 0.f;
            #pragma unroll
            for (int k = 0; k < 8; k++) {
                float4 r4 = row[k];
                acc += r4.x * tgt[k * 4 + 0] + r4.y * tgt[k * 4 + 1]
                     + r4.z * tgt[k * 4 + 2] + r4.w * tgt[k * 4 + 3];
            }
            s = acc;
        }
        sc[i] = s;
    }
    __syncthreads();

    // local max
    float m = -1e30f;
    for (int i = t; i < R; i += 256) m = fmaxf(m, sc[i]);
    #pragma unroll
    for (int off = 16; off > 0; off >>= 1)
        m = fmaxf(m, __shfl_xor_sync(0xffffffffu, m, off));
    if (lane == 0) red[w] = m;
    __syncthreads();
    if (t < 8) {
        float mm = red[t];
        #pragma unroll
        for (int off = 4; off > 0; off >>= 1)
            mm = fmaxf(mm, __shfl_xor_sync(0xffu, mm, off));
        red[t] = mm;
    }
    __syncthreads();
    float mloc = red[0];
    __syncthreads();

    if (mloc < -1e29f) {                          // empty sub-block
        if (t == 0) { g_pm[blockIdx.x] = -1e30f; g_ps[blockIdx.x] = 0.f; }
        if (t < D) g_pv[blockIdx.x * D + t] = 0.f;
        return;
    }

    // exp + local sum
    float ssum = 0.f;
    for (int i = t; i < R; i += 256) {
        float e = (sc[i] > -1e29f) ? __expf(sc[i] - mloc) : 0.f;
        sc[i] = e;
        ssum += e;
    }
    #pragma unroll
    for (int off = 16; off > 0; off >>= 1)
        ssum += __shfl_xor_sync(0xffffffffu, ssum, off);
    if (lane == 0) red[w] = ssum;
    __syncthreads();
    if (t < 8) {
        float s2 = red[t];
        #pragma unroll
        for (int off = 4; off > 0; off >>= 1)
            s2 += __shfl_xor_sync(0xffu, s2, off);
        red[t] = s2;
    }
    __syncthreads();
    float sloc = red[0];

    // weighted partial: 8 warps stride rows, lane = dim
    float a = 0.f;
    for (int i = w; i < R; i += 8) {
        float e = sc[i];
        if (e == 0.f) continue;
        a += e * g_nf[(rbase + i) * D + lane];
    }
    wacc[w][lane] = a;
    __syncthreads();
    if (t < D) {
        float acc = 0.f;
        #pragma unroll
        for (int q = 0; q < 8; q++) acc += wacc[q][t];
        g_pv[blockIdx.x * D + t] = acc;
    }
    if (t == 0) { g_pm[blockIdx.x] = mloc; g_ps[blockIdx.x] = sloc; }
}

// ---------------- path softmax phase B: combine + g_cnt reset ----------------
__global__ void k_path2(const float* __restrict__ zero_path, float* __restrict__ out) {
    int b = blockIdx.x, t = threadIdx.x;          // 32 threads
    if (b == 0 && t == 0) g_cnt = 0;              // restore invariant for next call
    float M = -1e30f;
    #pragma unroll
    for (int j = 0; j < SPLIT; j++) M = fmaxf(M, g_pm[b * SPLIT + j]);
    if (M < -1e29f) {
        out[OUT3_OFF + b * D + t] = zero_path[t];
        return;
    }
    float S = 0.f, v = 0.f;
    #pragma unroll
    for (int j = 0; j < SPLIT; j++) {
        float sc = __expf(g_pm[b * SPLIT + j] - M);
        S += sc * g_ps[b * SPLIT + j];
        v += sc * g_pv[(b * SPLIT + j) * D + t];
    }
    out[OUT3_OFF + b * D + t] = v / S;
}

// ---------------- launch ----------------
extern "C" void kernel_launch(void* const* d_in, const int* in_sizes, int n_in,
                              void* d_out, int out_size) {
    const float* feat = (const float*)d_in[0];
    const float* norm = (const float*)d_in[1];
    const float* W_w  = (const float*)d_in[2];
    const float* b_w  = (const float*)d_in[3];
    const float* W2   = (const float*)d_in[4];
    const float* b2   = (const float*)d_in[5];
    const float* attn = (const float*)d_in[6];
    const float* SL   = (const float*)d_in[7];
    const float* Wl   = (const float*)d_in[8];
    const float* bl   = (const float*)d_in[9];
    const float* zp   = (const float*)d_in[10];
    const int*   src  = (const int*)d_in[11];
    const int*   dst  = (const int*)d_in[12];
    const int*   ety  = (const int*)d_in[13];
    const int*   idx1 = (const int*)d_in[14];
    const int*   idx2 = (const int*)d_in[15];
    const int*   f2   = (const int*)d_in[16];
    const int*   tar  = (const int*)d_in[17];

    int nE     = in_sizes[11];
    int nNodes = in_sizes[0] / D;
    float* out = (float*)d_out;

    k_init<<<1184, 256>>>(feat, W_w, b_w, W2, b2, attn, SL, Wl, out, idx1, idx2, tar, nNodes);
    k_edge<<<1184, 256>>>(src, dst, ety, norm, attn, nE);
    k_nf  <<<520, 256>>>(feat, bl, idx1, idx2, f2, tar, out);
    k_path1<<<NBATCH * SPLIT, 256>>>(idx1, out);
    k_path2<<<NBATCH, 32>>>(zp, out);
}

// round 5
// speedup vs baseline: 2.8355x; 1.0506x over previous
#include <cuda_runtime.h>

#define N_NODES 131072
#define NPER    4096
#define NBATCH  32
#define D       32
#define NREL    10
#define NG      14   // num_g_rels
#define SPLIT   16   // path sub-blocks per batch
#define NE_MAX  2097152
#define OUT2_OFF (NBATCH * (NG + 1) * D)         // 15360
#define OUT3_OFF (OUT2_OFF + NBATCH * D)         // 16384

// ---------------- scratch (device globals; no allocation allowed) ----------------
__device__ __align__(16) float g_w1[N_NODES * D];
__device__ __align__(16) float g_U [N_NODES * D];
__device__ __align__(16) float g_V [N_NODES * D];
__device__ __align__(16) float g_S [N_NODES * 16];   // per-(node, rel) norm sums (16 pad)
__device__ __align__(16) float g_nf[N_NODES * D];
__device__ __align__(16) unsigned long long g_ep[NE_MAX];  // packed (norm | rel | src) by dst
__device__ int   g_deg[N_NODES];                 // invariant: 0 at kernel_launch entry
__device__ int   g_off[N_NODES];
__device__ int   g_cur[N_NODES];
__device__ int   g_bsum[512];
__device__ int   g_bsum2[512];
__device__ int   g_list[N_NODES];                // compacted active-node indices
__device__ int   g_cnt;                          // invariant: 0 at kernel_launch entry
__device__ float g_M1[D * D];     // (W2a - W2b) @ W_line
__device__ float g_M2[D * D];     // W2c @ W_line
__device__ float g_M3[D * D];     // self_loop_w @ W_line
__device__ float g_Cw[NREL * D];  // (attn_r @ (W2a+W2b) + b2) @ W_line
__device__ float g_pm[NBATCH * SPLIT];
__device__ float g_ps[NBATCH * SPLIT];
__device__ __align__(16) float g_pv[NBATCH * SPLIT * D];

__device__ __forceinline__ void red_add_v4(float* p, float4 v) {
    asm volatile("red.global.add.v4.f32 [%0], {%1,%2,%3,%4};"
                 :: "l"(p), "f"(v.x), "f"(v.y), "f"(v.z), "f"(v.w) : "memory");
}
__device__ __forceinline__ float fsel(const float4& q, int c) {
    return c == 0 ? q.x : (c == 1 ? q.y : (c == 2 ? q.z : q.w));
}

// ---------------- init: prep (block 0) + zero out + compaction + w1 + dst histogram ----------------
__global__ void k_init(const float* __restrict__ feat, const float* __restrict__ Ww,
                       const float* __restrict__ bw,
                       const float* __restrict__ W2, const float* __restrict__ b2,
                       const float* __restrict__ attn, const float* __restrict__ SL,
                       const float* __restrict__ Wl,
                       float* __restrict__ out,
                       const int* __restrict__ idx1, const int* __restrict__ idx2,
                       const int* __restrict__ tar, const int* __restrict__ dst,
                       int n_nodes, int nE) {
    // ---- prep (block 0 only): derived matrices ----
    if (blockIdx.x == 0) {
        __shared__ float Cs[NREL * D];
        int t = threadIdx.x;
        for (int i = t; i < NREL * D; i += blockDim.x) {
            int r = i / D, j = i % D;
            float acc = b2[j];
            #pragma unroll
            for (int k = 0; k < D; k++)
                acc += attn[r * D + k] * (W2[k * D + j] + W2[(D + k) * D + j]);
            Cs[i] = acc;
        }
        __syncthreads();
        for (int i = t; i < D * D; i += blockDim.x) {
            int k = i / D, d = i % D;
            float m1 = 0.f, m2 = 0.f, m3 = 0.f;
            #pragma unroll
            for (int j = 0; j < D; j++) {
                float wl = Wl[j * D + d];
                m1 += (W2[k * D + j] - W2[(D + k) * D + j]) * wl;
                m2 += W2[(2 * D + k) * D + j] * wl;
                m3 += SL[k * D + j] * wl;
            }
            g_M1[i] = m1; g_M2[i] = m2; g_M3[i] = m3;
        }
        for (int i = t; i < NREL * D; i += blockDim.x) {
            int r = i / D, d = i % D;
            float acc = 0.f;
            #pragma unroll
            for (int j = 0; j < D; j++) acc += Cs[r * D + j] * Wl[j * D + d];
            g_Cw[i] = acc;
        }
    }

    int tid = blockIdx.x * blockDim.x + threadIdx.x;
    int stride = gridDim.x * blockDim.x;
    if (tid < OUT3_OFF) out[tid] = 0.f;

    // ---- dst histogram (g_deg == 0 at entry) ----
    for (int e = tid; e < nE; e += stride)
        atomicAdd(&g_deg[__ldg(&dst[e])], 1);

    // ---- active-node compaction (warp-aggregated; g_cnt == 0 at entry) ----
    {
        int n = tid;                              // stride >= n_nodes
        bool active = false;
        if (n < n_nodes)
            active = (__ldg(&idx1[n]) == 1) || (__ldg(&idx2[n]) != 0) || (__ldg(&tar[n]) == 1);
        unsigned m = __ballot_sync(0xffffffffu, active);
        if (m) {
            int lane = threadIdx.x & 31;
            int rank = __popc(m & ((1u << lane) - 1u));
            int base = 0;
            if (lane == __ffs(m) - 1) base = atomicAdd(&g_cnt, __popc(m));
            base = __shfl_sync(0xffffffffu, base, __ffs(m) - 1);
            if (active) g_list[base + rank] = n;
        }
    }

    // ---- w1 = feat @ W_w + b_w : 16 nodes/warp (4 per 8-lane group) ----
    __shared__ __align__(16) float Ws[D * D];
    for (int i = threadIdx.x; i < D * D; i += blockDim.x) Ws[i] = Ww[i];
    __syncthreads();
    const float4* Ws4 = reinterpret_cast<const float4*>(Ws);
    int lane = threadIdx.x & 31;
    int sub  = lane & 7;
    int grp  = lane >> 3;
    int warp = tid >> 5;
    int nw   = stride >> 5;
    float4 b4 = __ldg(reinterpret_cast<const float4*>(bw) + sub);
    for (int base = warp * 16; base < n_nodes; base += nw * 16) {
        float4 f4[4], acc[4];
        #pragma unroll
        for (int t = 0; t < 4; t++) {
            int n = base + grp * 4 + t;           // n_nodes % 16 == 0
            f4[t]  = *reinterpret_cast<const float4*>(&feat[n * D + sub * 4]);
            acc[t] = b4;
        }
        #pragma unroll
        for (int k = 0; k < D; k++) {
            float4 w = Ws4[k * 8 + sub];
            #pragma unroll
            for (int t = 0; t < 4; t++) {
                float fk = __shfl_sync(0xffffffffu, fsel(f4[t], k & 3), k >> 2, 8);
                acc[t].x += fk * w.x; acc[t].y += fk * w.y;
                acc[t].z += fk * w.z; acc[t].w += fk * w.w;
            }
        }
        #pragma unroll
        for (int t = 0; t < 4; t++) {
            int n = base + grp * 4 + t;
            *reinterpret_cast<float4*>(&g_w1[n * D + sub * 4]) = acc[t];
        }
    }
}

// ---------------- scan 1: per-256-block exclusive scan of g_deg ----------------
__global__ void k_scan1() {                       // <<<512, 256>>>
    __shared__ int sh[256];
    int i = blockIdx.x * 256 + threadIdx.x;
    int v = g_deg[i];
    sh[threadIdx.x] = v;
    __syncthreads();
    #pragma unroll
    for (int off = 1; off < 256; off <<= 1) {
        int t = (threadIdx.x >= off) ? sh[threadIdx.x - off] : 0;
        __syncthreads();
        sh[threadIdx.x] += t;
        __syncthreads();
    }
    g_off[i] = sh[threadIdx.x] - v;               // exclusive
    if (threadIdx.x == 255) g_bsum[blockIdx.x] = sh[255];
}

// ---------------- scan 2: exclusive scan of 512 block sums ----------------
__global__ void k_scan2() {                       // <<<1, 512>>>
    __shared__ int sh[512];
    int t = threadIdx.x;
    int v = g_bsum[t];
    sh[t] = v;
    __syncthreads();
    #pragma unroll
    for (int off = 1; off < 512; off <<= 1) {
        int x = (t >= off) ? sh[t - off] : 0;
        __syncthreads();
        sh[t] += x;
        __syncthreads();
    }
    g_bsum2[t] = sh[t] - v;                       // exclusive
}

// ---------------- scan 3: add back block offsets, init cursors ----------------
__global__ void k_scan3() {                       // <<<512, 256>>>
    int i = blockIdx.x * 256 + threadIdx.x;
    int o = g_off[i] + g_bsum2[blockIdx.x];
    g_off[i] = o;
    g_cur[i] = o;
}

// ---------------- scatter edges into dst-sorted packed array ----------------
__global__ void k_scatter(const int* __restrict__ src, const int* __restrict__ dst,
                          const int* __restrict__ ety, const float* __restrict__ norm,
                          int nE) {
    int tid = blockIdx.x * blockDim.x + threadIdx.x;
    int stride = gridDim.x * blockDim.x;
    for (int e = tid; e < nE; e += stride) {
        int d = __ldg(&dst[e]);
        int p = atomicAdd(&g_cur[d], 1);
        unsigned lo = (unsigned)__ldg(&src[e]) | ((unsigned)__ldg(&ety[e]) << 20);
        unsigned long long pk =
            ((unsigned long long)__float_as_uint(__ldg(&norm[e])) << 32) | lo;
        g_ep[p] = pk;
    }
}

// ---------------- edge stage: 8-lane group per dst, register accumulation, plain stores ----------------
__global__ void k_edge2(const float* __restrict__ attn, int n_nodes) {
    __shared__ float4 et_s[NREL * 8];
    for (int i = threadIdx.x; i < NREL * 8; i += blockDim.x)
        et_s[i] = reinterpret_cast<const float4*>(attn)[i];
    __syncthreads();
    int lane = threadIdx.x & 31;
    int sub  = lane & 7;
    int grp  = lane >> 3;
    unsigned gmask = 0xFFu << (grp * 8);
    int gid  = (blockIdx.x * blockDim.x + threadIdx.x) >> 3;
    int ng   = (gridDim.x * blockDim.x) >> 3;
    const float4 z = make_float4(0.f, 0.f, 0.f, 0.f);

    for (int d = gid; d < n_nodes; d += ng) {
        int deg   = g_deg[d];
        int start = g_off[d];
        float4 aU = z, aV = z;
        float s0 = 0.f, s1 = 0.f;
        for (int base = 0; base < deg; base += 8) {
            int rem = deg - base;
            unsigned long long pk = 0ull;
            if (sub < rem) pk = g_ep[start + base + sub];
            if (rem >= 8) {
                #pragma unroll
                for (int j = 0; j < 8; j++) {
                    unsigned long long pj = __shfl_sync(gmask, pk, j, 8);
                    unsigned lo = (unsigned)pj;
                    float nm = __uint_as_float((unsigned)(pj >> 32));
                    int s = lo & 0xFFFFF;
                    int r = (int)(lo >> 20);
                    float4 f = *reinterpret_cast<const float4*>(&g_w1[s * D + sub * 4]);
                    float4 et = et_s[r * 8 + sub];
                    aU.x += nm * f.x; aU.y += nm * f.y; aU.z += nm * f.z; aU.w += nm * f.w;
                    aV.x += nm * et.x * f.x; aV.y += nm * et.y * f.y;
                    aV.z += nm * et.z * f.z; aV.w += nm * et.w * f.w;
                    s0 += (r == sub)     ? nm : 0.f;
                    s1 += (r == sub + 8) ? nm : 0.f;
                }
            } else {
                for (int j = 0; j < rem; j++) {
                    unsigned long long pj = __shfl_sync(gmask, pk, j, 8);
                    unsigned lo = (unsigned)pj;
                    float nm = __uint_as_float((unsigned)(pj >> 32));
                    int s = lo & 0xFFFFF;
                    int r = (int)(lo >> 20);
                    float4 f = *reinterpret_cast<const float4*>(&g_w1[s * D + sub * 4]);
                    float4 et = et_s[r * 8 + sub];
                    aU.x += nm * f.x; aU.y += nm * f.y; aU.z += nm * f.z; aU.w += nm * f.w;
                    aV.x += nm * et.x * f.x; aV.y += nm * et.y * f.y;
                    aV.z += nm * et.z * f.z; aV.w += nm * et.w * f.w;
                    s0 += (r == sub)     ? nm : 0.f;
                    s1 += (r == sub + 8) ? nm : 0.f;
                }
            }
        }
        *reinterpret_cast<float4*>(&g_U[d * D + sub * 4]) = aU;
        *reinterpret_cast<float4*>(&g_V[d * D + sub * 4]) = aV;
        g_S[d * 16 + sub]     = s0;
        g_S[d * 16 + 8 + sub] = s1;
        if (sub == 0) g_deg[d] = 0;               // restore invariant for next call
    }
}

// ---------------- combine + scatter over compacted list: 16 nodes/warp ----------------
__global__ void __launch_bounds__(256, 2)
k_nf(const float* __restrict__ feat, const float* __restrict__ bline,
     const int* __restrict__ idx1, const int* __restrict__ idx2,
     const int* __restrict__ f2, const int* __restrict__ tar,
     float* __restrict__ out) {
    __shared__ __align__(16) float M1s[D * D], M2s[D * D], M3s[D * D], Cws[NREL * D];
    for (int i = threadIdx.x; i < D * D; i += blockDim.x) {
        M1s[i] = g_M1[i]; M2s[i] = g_M2[i]; M3s[i] = g_M3[i];
    }
    for (int i = threadIdx.x; i < NREL * D; i += blockDim.x) Cws[i] = g_Cw[i];
    __syncthreads();
    const float4* M14 = reinterpret_cast<const float4*>(M1s);
    const float4* M24 = reinterpret_cast<const float4*>(M2s);
    const float4* M34 = reinterpret_cast<const float4*>(M3s);
    const float4* Cw4 = reinterpret_cast<const float4*>(Cws);
    int cnt  = g_cnt;
    int lane = threadIdx.x & 31;
    int sub  = lane & 7;
    int grp  = lane >> 3;
    int warp = (blockIdx.x * blockDim.x + threadIdx.x) >> 5;
    int nw   = (gridDim.x * blockDim.x) >> 5;
    float4 b4 = __ldg(reinterpret_cast<const float4*>(bline) + sub);

    for (int base = warp * 16; base < cnt; base += nw * 16) {
        int  n_t[4];
        bool val_t[4];
        float4 acc[4];
        #pragma unroll
        for (int t = 0; t < 4; t++) {
            int i = base + grp * 4 + t;
            val_t[t] = i < cnt;
            n_t[t] = g_list[val_t[t] ? i : 0];
            acc[t] = b4;
        }
        {
            float sv0[4], sv1[4];
            #pragma unroll
            for (int t = 0; t < 4; t++) {
                sv0[t] = g_S[n_t[t] * 16 + sub];
                sv1[t] = g_S[n_t[t] * 16 + 8 + sub];
            }
            #pragma unroll
            for (int r = 0; r < NREL; r++) {
                float4 c = Cw4[r * 8 + sub];
                #pragma unroll
                for (int t = 0; t < 4; t++) {
                    float s_r = __shfl_sync(0xffffffffu, r < 8 ? sv0[t] : sv1[t], r & 7, 8);
                    acc[t].x += s_r * c.x; acc[t].y += s_r * c.y;
                    acc[t].z += s_r * c.z; acc[t].w += s_r * c.w;
                }
            }
        }
        {
            float4 u4[4], v4[4], f4[4];
            #pragma unroll
            for (int t = 0; t < 4; t++) {
                u4[t] = *reinterpret_cast<const float4*>(&g_U[n_t[t] * D + sub * 4]);
                v4[t] = *reinterpret_cast<const float4*>(&g_V[n_t[t] * D + sub * 4]);
                f4[t] = *reinterpret_cast<const float4*>(&feat[n_t[t] * D + sub * 4]);
            }
            #pragma unroll
            for (int k = 0; k < D; k++) {
                float4 m1 = M14[k * 8 + sub];
                float4 m2 = M24[k * 8 + sub];
                float4 m3 = M34[k * 8 + sub];
                #pragma unroll
                for (int t = 0; t < 4; t++) {
                    float uk = __shfl_sync(0xffffffffu, fsel(u4[t], k & 3), k >> 2, 8);
                    float vk = __shfl_sync(0xffffffffu, fsel(v4[t], k & 3), k >> 2, 8);
                    float fk = __shfl_sync(0xffffffffu, fsel(f4[t], k & 3), k >> 2, 8);
                    acc[t].x += uk * m1.x + vk * m2.x + fk * m3.x;
                    acc[t].y += uk * m1.y + vk * m2.y + fk * m3.y;
                    acc[t].z += uk * m1.z + vk * m2.z + fk * m3.z;
                    acc[t].w += uk * m1.w + vk * m2.w + fk * m3.w;
                }
            }
        }
        #pragma unroll
        for (int t = 0; t < 4; t++) {
            if (!val_t[t]) continue;
            int n = n_t[t];
            float4 val = make_float4(fmaxf(acc[t].x, 0.f), fmaxf(acc[t].y, 0.f),
                                     fmaxf(acc[t].z, 0.f), fmaxf(acc[t].w, 0.f));
            int b  = n >> 12;                     // n / NPER
            int i1 = __ldg(&idx1[n]);
            int i2 = __ldg(&idx2[n]);
            int tr = __ldg(&tar[n]);
            if (i1 == 1)
                *reinterpret_cast<float4*>(&g_nf[n * D + sub * 4]) = val;
            if (i2 != 0) {
                int slot = __ldg(&f2[n]) + 1;     // index_offset = 1
                if (slot <= NG)                   // slot NG+1 = dump row (dropped)
                    *reinterpret_cast<float4*>(&out[(b * (NG + 1) + slot) * D + sub * 4]) = val;
            }
            if (tr == 1)
                red_add_v4(&out[OUT2_OFF + b * D + sub * 4], val);
        }
    }
}

// ---------------- path softmax phase A: per-sub-block max/sum/partial ----------------
__global__ void k_path1(const int* __restrict__ idx1, const float* __restrict__ out) {
    const int R = NPER / SPLIT;                   // 256 rows per block
    __shared__ float sc[R];
    __shared__ float tgt[D];
    __shared__ float red[8];
    __shared__ float wacc[8][D];
    int b = blockIdx.x / SPLIT, j = blockIdx.x % SPLIT;
    int t = threadIdx.x;
    int w = t >> 5, lane = t & 31;
    if (t < D) tgt[t] = out[OUT2_OFF + b * D + t];
    __syncthreads();
    size_t rbase = (size_t)b * NPER + (size_t)j * R;

    for (int i = t; i < R; i += 256) {
        float s = -1e30f;
        if (idx1[rbase + i] == 1) {
            const float4* row = reinterpret_cast<const float4*>(g_nf + (rbase + i) * D);
            float acc = 0.f;
            #pragma unroll
            for (int k = 0; k < 8; k++) {
                float4 r4 = row[k];
                acc += r4.x * tgt[k * 4 + 0] + r4.y * tgt[k * 4 + 1]
                     + r4.z * tgt[k * 4 + 2] + r4.w * tgt[k * 4 + 3];
            }
            s = acc;
        }
        sc[i] = s;
    }
    __syncthreads();

    float m = -1e30f;
    for (int i = t; i < R; i += 256) m = fmaxf(m, sc[i]);
    #pragma unroll
    for (int off = 16; off > 0; off >>= 1)
        m = fmaxf(m, __shfl_xor_sync(0xffffffffu, m, off));
    if (lane == 0) red[w] = m;
    __syncthreads();
    if (t < 8) {
        float mm = red[t];
        #pragma unroll
        for (int off = 4; off > 0; off >>= 1)
            mm = fmaxf(mm, __shfl_xor_sync(0xffu, mm, off));
        red[t] = mm;
    }
    __syncthreads();
    float mloc = red[0];
    __syncthreads();

    if (mloc < -1e29f) {
        if (t == 0) { g_pm[blockIdx.x] = -1e30f; g_ps[blockIdx.x] = 0.f; }
        if (t < D) g_pv[blockIdx.x * D + t] = 0.f;
        return;
    }

    float ssum = 0.f;
    for (int i = t; i < R; i += 256) {
        float e = (sc[i] > -1e29f) ? __expf(sc[i] - mloc) : 0.f;
        sc[i] = e;
        ssum += e;
    }
    #pragma unroll
    for (int off = 16; off > 0; off >>= 1)
        ssum += __shfl_xor_sync(0xffffffffu, ssum, off);
    if (lane == 0) red[w] = ssum;
    __syncthreads();
    if (t < 8) {
        float s2 = red[t];
        #pragma unroll
        for (int off = 4; off > 0; off >>= 1)
            s2 += __shfl_xor_sync(0xffu, s2, off);
        red[t] = s2;
    }
    __syncthreads();
    float sloc = red[0];

    float a = 0.f;
    for (int i = w; i < R; i += 8) {
        float e = sc[i];
        if (e == 0.f) continue;
        a += e * g_nf[(rbase + i) * D + lane];
    }
    wacc[w][lane] = a;
    __syncthreads();
    if (t < D) {
        float acc = 0.f;
        #pragma unroll
        for (int q = 0; q < 8; q++) acc += wacc[q][t];
        g_pv[blockIdx.x * D + t] = acc;
    }
    if (t == 0) { g_pm[blockIdx.x] = mloc; g_ps[blockIdx.x] = sloc; }
}

// ---------------- path softmax phase B: combine + g_cnt reset ----------------
__global__ void k_path2(const float* __restrict__ zero_path, float* __restrict__ out) {
    int b = blockIdx.x, t = threadIdx.x;          // 32 threads
    if (b == 0 && t == 0) g_cnt = 0;              // restore invariant for next call
    float M = -1e30f;
    #pragma unroll
    for (int j = 0; j < SPLIT; j++) M = fmaxf(M, g_pm[b * SPLIT + j]);
    if (M < -1e29f) {
        out[OUT3_OFF + b * D + t] = zero_path[t];
        return;
    }
    float S = 0.f, v = 0.f;
    #pragma unroll
    for (int j = 0; j < SPLIT; j++) {
        float sc = __expf(g_pm[b * SPLIT + j] - M);
        S += sc * g_ps[b * SPLIT + j];
        v += sc * g_pv[(b * SPLIT + j) * D + t];
    }
    out[OUT3_OFF + b * D + t] = v / S;
}

// ---------------- launch ----------------
extern "C" void kernel_launch(void* const* d_in, const int* in_sizes, int n_in,
                              void* d_out, int out_size) {
    const float* feat = (const float*)d_in[0];
    const float* norm = (const float*)d_in[1];
    const float* W_w  = (const float*)d_in[2];
    const float* b_w  = (const float*)d_in[3];
    const float* W2   = (const float*)d_in[4];
    const float* b2   = (const float*)d_in[5];
    const float* attn = (const float*)d_in[6];
    const float* SL   = (const float*)d_in[7];
    const float* Wl   = (const float*)d_in[8];
    const float* bl   = (const float*)d_in[9];
    const float* zp   = (const float*)d_in[10];
    const int*   src  = (const int*)d_in[11];
    const int*   dst  = (const int*)d_in[12];
    const int*   ety  = (const int*)d_in[13];
    const int*   idx1 = (const int*)d_in[14];
    const int*   idx2 = (const int*)d_in[15];
    const int*   f2   = (const int*)d_in[16];
    const int*   tar  = (const int*)d_in[17];

    int nE     = in_sizes[11];
    int nNodes = in_sizes[0] / D;
    float* out = (float*)d_out;

    k_init<<<1184, 256>>>(feat, W_w, b_w, W2, b2, attn, SL, Wl, out,
                          idx1, idx2, tar, dst, nNodes, nE);
    k_scan1<<<512, 256>>>();
    k_scan2<<<1, 512>>>();
    k_scan3<<<512, 256>>>();
    k_scatter<<<1184, 256>>>(src, dst, ety, norm, nE);
    k_edge2<<<1184, 256>>>(attn, nNodes);
    k_nf  <<<520, 256>>>(feat, bl, idx1, idx2, f2, tar, out);
    k_path1<<<NBATCH * SPLIT, 256>>>(idx1, out);
    k_path2<<<NBATCH, 32>>>(zp, out);
}